// round 12
// baseline (speedup 1.0000x reference)
#include <cuda_runtime.h>
#include <cfloat>
#include <stdint.h>

#define BS    8
#define NQ    16384
#define NG    1024
#define TOPK  4
#define NBIN  1024
#define BINW  0.0009765625f     // 1/1024
#define STEP  64
#define NTOT  (BS * NQ)         // 131072
#define NBG   (BS * NG)         // 8192
#define COST_POINT 0.1f
#define REG_COEF   5.0f

// -------- scratch (static device globals) --------
__device__ float4 g_packed[NTOT];          // {-2x, -2y, |p|^2, prob0}
__device__ float  g_prob[NTOT];
__device__ float2 g_xy[NTOT];              // exact coords for reg loss
__device__ float  g_lp0[NTOT];
__device__ float  g_lp1[NTOT];
__device__ unsigned char g_flag[NTOT];
__device__ float4 g_cand4[BS][NQ];         // candidates, descending-prob bucket order
__device__ int    g_candq[BS][NQ];
__device__ int    g_pos[BS][NBIN];         // bucket write cursors (init = bases)
__device__ int    g_tbin[BS];
__device__ int    g_ncand[BS];
__device__ float  g_regp[NBG];
__device__ float  g_part[3 * 128];
__device__ int    g_done;
__device__ int    g_mi32;

__device__ __forceinline__ int mask_at(const void* m, int i, int is_i32) {
    return is_i32 ? (((const int*)m)[i] != 0) : (((const unsigned char*)m)[i] != 0);
}

// -------- prep: per-(b,q) precompute + zero scratch + fused mask-dtype detect ----
__global__ void __launch_bounds__(256) prep_kernel(
    const float* __restrict__ pc, const float* __restrict__ pl,
    const unsigned char* __restrict__ m)
{
    int t = threadIdx.x;
    if (blockIdx.x == 0) {
        int bad = ((t & 3) != 0) && (m[t] != 0);
        int any = __syncthreads_or(bad);
        if (t == 0) { g_mi32 = !any; g_done = 0; }
    }
    int i = blockIdx.x * blockDim.x + t;
    if (i >= NTOT) return;
    float2 c  = ((const float2*)pc)[i];
    float2 lg = ((const float2*)pl)[i];
    float x = c.x, y = c.y, l0 = lg.x, l1 = lg.y;
    float mm = fmaxf(l0, l1);
    float e0 = expf(l0 - mm);
    float e1 = expf(l1 - mm);
    float s  = __fadd_rn(e0, e1);
    float p0 = __fdiv_rn(e0, s);
    float ls = logf(s);
    float pp = __fadd_rn(__fmul_rn(x, x), __fmul_rn(y, y));
    g_packed[i] = make_float4(__fmul_rn(-2.0f, x), __fmul_rn(-2.0f, y), pp, p0);
    g_prob[i] = p0;
    g_xy[i] = make_float2(x, y);
    g_lp0[i] = __fadd_rn(__fadd_rn(l0, -mm), -ls);
    g_lp1[i] = __fadd_rn(__fadd_rn(l1, -mm), -ls);
    g_flag[i] = 0;
    if (i < NBG) g_regp[i] = 0.0f;
}

// -------- setup: per-batch prob histogram, p4 threshold, bucket bases --------
__global__ void __launch_bounds__(256) setup_kernel() {
    int b = blockIdx.x;
    int t = threadIdx.x;
    __shared__ int hist[NBIN];
    __shared__ int ls[256];
    __shared__ int p4bin;
    __shared__ int stbin;
    #pragma unroll
    for (int j = 0; j < 4; j++) hist[t * 4 + j] = 0;
    if (t == 0) p4bin = 0;
    __syncthreads();
    for (int j = 0; j < 64; j++) {
        float p = g_prob[b * NQ + j * 256 + t];
        int bin = min(NBIN - 1, (int)(p * 1024.0f));
        atomicAdd(&hist[bin], 1);
    }
    __syncthreads();
    // thread t owns bins [4t..4t+3]; build suffix sums S[i] = sum_{j>=i} hist[j]
    int h0 = hist[4 * t], h1 = hist[4 * t + 1], h2 = hist[4 * t + 2], h3 = hist[4 * t + 3];
    ls[t] = h0 + h1 + h2 + h3;
    __syncthreads();
    for (int o = 1; o < 256; o <<= 1) {
        int v = (t + o < 256) ? ls[t + o] : 0;
        __syncthreads();
        ls[t] += v;
        __syncthreads();
    }
    int excl = (t + 1 < 256) ? ls[t + 1] : 0;   // sum over threads > t
    int S3 = excl + h3;
    int S2 = S3 + h2;
    int S1 = S2 + h1;
    int S0 = S1 + h0;
    // p4bin = max bin with S[bin] >= 4
    int cand = -1;
    if      (S3 >= 4) cand = 4 * t + 3;
    else if (S2 >= 4) cand = 4 * t + 2;
    else if (S1 >= 4) cand = 4 * t + 1;
    else if (S0 >= 4) cand = 4 * t;
    if (cand >= 0) atomicMax(&p4bin, cand);
    __syncthreads();
    if (t == 0) {
        float lo4 = (float)p4bin * BINW;             // lower bound on p4
        float thresh = lo4 - 0.141422f;              // p4 - 0.1*sqrt(2), conservative
        int tb = (int)floorf(thresh * 1024.0f);
        if (tb < 0) tb = 0;
        stbin = tb;
        g_tbin[b] = tb;
    }
    __syncthreads();
    int tb = stbin;
    // bucket base (descending order): base[bin] = S[bin+1]
    if (4 * t     >= tb) g_pos[b][4 * t]     = S1;
    if (4 * t + 1 >= tb) g_pos[b][4 * t + 1] = S2;
    if (4 * t + 2 >= tb) g_pos[b][4 * t + 2] = S3;
    if (4 * t + 3 >= tb) g_pos[b][4 * t + 3] = excl;
    if (tb >= 4 * t && tb <= 4 * t + 3) {
        int Stb = (tb == 4 * t) ? S0 : (tb == 4 * t + 1) ? S1 : (tb == 4 * t + 2) ? S2 : S3;
        g_ncand[b] = Stb;
    }
}

// -------- scatter: counting-sort kept candidates into descending-prob buckets ----
__global__ void __launch_bounds__(256) scatter_kernel() {
    int i = blockIdx.x * 256 + threadIdx.x;
    int b = i >> 14;
    float p = g_prob[i];
    int bin = min(NBIN - 1, (int)(p * 1024.0f));
    if (bin >= g_tbin[b]) {
        int slot = atomicAdd(&g_pos[b][bin], 1);
        g_cand4[b][slot] = g_packed[i];
        g_candq[b][slot] = i & (NQ - 1);
    }
}

// orderable-uint mapping and inverse
__device__ __forceinline__ unsigned int float_key(float f) {
    unsigned int u = __float_as_uint(f);
    return u ^ (((int)u < 0) ? 0xFFFFFFFFu : 0x80000000u);
}
__device__ __forceinline__ float key_to_float(unsigned int k) {
    return __uint_as_float(k ^ ((k & 0x80000000u) ? 0x80000000u : 0xFFFFFFFFu));
}

#define KEY_SENTINEL 0xFF7FFFFFFFFFFFFFull   // (float_key(FLT_MAX)<<32) | 0xFFFFFFFF

// snapshot-exchange merge of two sorted-4 lists across shfl distance d.
// Valid ONLY for disjoint lists; used at scan end where stage-d unions are
// disjoint (distinct q => distinct keys).
#define QUAD_MERGE(d)                                                          \
    {                                                                          \
        unsigned long long s0 = k0, s1 = k1, s2 = k2, s3 = k3;                 \
        unsigned long long p0 = __shfl_xor_sync(0xFFFFFFFFu, s0, d);           \
        unsigned long long p1 = __shfl_xor_sync(0xFFFFFFFFu, s1, d);           \
        unsigned long long p2 = __shfl_xor_sync(0xFFFFFFFFu, s2, d);           \
        unsigned long long p3 = __shfl_xor_sync(0xFFFFFFFFu, s3, d);           \
        unsigned long long ps[4] = {p0, p1, p2, p3};                           \
        _Pragma("unroll")                                                      \
        for (int r = 0; r < 4; r++) {                                          \
            unsigned long long pk = ps[r];                                     \
            if (pk < k3) {                                                     \
                if (pk < k0)      { k3 = k2; k2 = k1; k1 = k0; k0 = pk; }      \
                else if (pk < k1) { k3 = k2; k2 = k1; k1 = pk; }               \
                else if (pk < k2) { k3 = k2; k2 = pk; }                        \
                else              { k3 = pk; }                                 \
            }                                                                  \
        }                                                                      \
    }

// -------- match: direct-global ordered scan, 8 threads/g, no block syncs.
// Warp-converged threshold min-share every STEP candidates; final 3-stage
// disjoint merge.
__global__ void __launch_bounds__(256) match_kernel(
    const float* __restrict__ gtc, const void* __restrict__ gtm)
{
    int blk = blockIdx.x;                 // 256 blocks: b*32 + sub
    int b   = blk >> 5;
    int sub = blk & 31;
    int t   = threadIdx.x;
    int par = t & 7;
    int g   = sub * 32 + (t >> 3);
    int bg  = b * NG + g;
    int active = mask_at(gtm, bg, g_mi32);
    int n = g_ncand[b];
    const float4* __restrict__ cand  = g_cand4[b];
    const int*    __restrict__ candq = g_candq[b];

    float2 gc = ((const float2*)gtc)[bg];
    float gx = gc.x, gy = gc.y;
    float gg = __fadd_rn(__fmul_rn(gx, gx), __fmul_rn(gy, gy));

    unsigned long long k0 = KEY_SENTINEL, k1 = KEY_SENTINEL,
                       k2 = KEY_SENTINEL, k3 = KEY_SENTINEL;
    float c3  = FLT_MAX;                      // valid upper bound on final c3
    float T   = __fmaf_rn(10.0f, c3, 1e-3f);
    float brk = -FLT_MAX;
    bool done = !active;

    for (int base = 0; base < n; base += STEP) {
        int lim = min(base + STEP, n);
        if (!done) {
            #pragma unroll 4
            for (int i = base + par; i < lim; i += 8) {
                float4 f = __ldg(&cand[i]);
                // descending prob (granularity BINW): all later candidates have
                // prob < f.w + BINW <= -c3  =>  cost > c3  => provably out
                if (f.w < brk) { done = true; break; }
                float h = __fmaf_rn(f.x, gx, __fmaf_rn(f.y, gy, f.z));
                float u = __fmaf_rn(10.0f, f.w, T);
                float v = __fmaf_rn(u, fabsf(u), -gg);
                if (h < v) {
                    // exact reference-literal cost
                    float x  = __fmul_rn(-0.5f, f.x), y = __fmul_rn(-0.5f, f.y);
                    float d  = __fmaf_rn(y, gy, __fmul_rn(x, gx));
                    float s1 = __fadd_rn(f.z, gg);
                    float sq = __fmaf_rn(-2.0f, d, s1);
                    float cost = __fadd_rn(__fmul_rn(COST_POINT, __fsqrt_rn(fmaxf(sq, 0.0f))), -f.w);
                    unsigned long long key =
                        ((unsigned long long)float_key(cost) << 32) | (unsigned int)__ldg(&candq[i]);
                    if (key < k3) {
                        if (key < k0)      { k3 = k2; k2 = k1; k1 = k0; k0 = key; }
                        else if (key < k1) { k3 = k2; k2 = k1; k1 = key; }
                        else if (key < k2) { k3 = k2; k2 = key; }
                        else               { k3 = key; }
                        // tighten, never loosen, the shared bound
                        c3  = fminf(c3, key_to_float((unsigned int)(k3 >> 32)));
                        T   = __fmaf_rn(10.0f, c3, 1e-3f);
                        brk = __fadd_rn(-c3, -BINW);
                    }
                }
            }
        }
        // warp-converged: min-share threshold across the 8 lanes of each g
        // (min of valid upper bounds is a valid upper bound; lists stay private)
        c3 = fminf(c3, __shfl_xor_sync(0xFFFFFFFFu, c3, 1));
        c3 = fminf(c3, __shfl_xor_sync(0xFFFFFFFFu, c3, 2));
        c3 = fminf(c3, __shfl_xor_sync(0xFFFFFFFFu, c3, 4));
        T   = __fmaf_rn(10.0f, c3, 1e-3f);
        brk = __fadd_rn(-c3, -BINW);
        if (__all_sync(0xFFFFFFFFu, done)) break;
    }

    // final merge of the 8 disjoint per-thread lists (each stage disjoint)
    QUAD_MERGE(1);
    QUAD_MERGE(2);
    QUAD_MERGE(4);

    if (active && par == 0) {
        float acc = 0.0f;
        unsigned long long ks[4] = {k0, k1, k2, k3};
        #pragma unroll
        for (int k = 0; k < TOPK; k++) {
            int q = (int)(unsigned int)(ks[k] & 0xFFFFFFFFull);
            g_flag[b * NQ + q] = 1;          // idempotent; races benign
            float2 p = g_xy[b * NQ + q];
            float dx = __fadd_rn(p.x, -gx), dy = __fadd_rn(p.y, -gy);
            acc = __fadd_rn(acc, __fadd_rn(__fmul_rn(dx, dx), __fmul_rn(dy, dy)));
        }
        g_regp[bg] = acc;
    }
}

// -------- reduce: per-block partials + last-block fixed-order finale --------
__global__ void __launch_bounds__(256) reduce_kernel(
    const void* __restrict__ gtm, float* __restrict__ out)
{
    int blk = blockIdx.x;
    int base = blk * 1024;
    int t = threadIdx.x;
    int mi32 = g_mi32;

    float cl = 0.0f, rg = 0.0f; int cn = 0;
    #pragma unroll
    for (int j = 0; j < 4; j++) {
        int i = base + j * 256 + t;
        cl += g_flag[i] ? g_lp0[i] : g_lp1[i];
    }
    if (base < NBG) {
        #pragma unroll
        for (int j = 0; j < 4; j++) {
            int i = base + j * 256 + t;
            rg += g_regp[i];
            cn += mask_at(gtm, i, mi32);
        }
    }
    __shared__ float s1[256], s2[256];
    __shared__ int   s3[256];
    s1[t] = cl; s2[t] = rg; s3[t] = cn;
    __syncthreads();
    for (int s = 128; s > 0; s >>= 1) {
        if (t < s) { s1[t] += s1[t + s]; s2[t] += s2[t + s]; s3[t] += s3[t + s]; }
        __syncthreads();
    }
    __shared__ bool s_last;
    if (t == 0) {
        g_part[blk]       = s1[0];
        g_part[128 + blk] = s2[0];
        g_part[256 + blk] = (float)s3[0];
        __threadfence();
        int old = atomicAdd(&g_done, 1);
        s_last = (old == 127);
    }
    __syncthreads();
    if (s_last) {
        __shared__ float a[128], bb[128], cc[128];
        if (t < 128) {
            a[t]  = g_part[t];
            bb[t] = g_part[128 + t];
            cc[t] = g_part[256 + t];
        }
        __syncthreads();
        for (int s = 64; s > 0; s >>= 1) {
            if (t < s) { a[t] += a[t + s]; bb[t] += bb[t + s]; cc[t] += cc[t + s]; }
            __syncthreads();
        }
        if (t == 0) {
            float n_valid = __fmul_rn(cc[0], (float)TOPK);
            out[0] = __fmul_rn(__fdiv_rn(bb[0], __fmul_rn(n_valid, 2.0f)), REG_COEF);
            out[1] = __fdiv_rn(-a[0], (float)NTOT);
        }
    }
}

extern "C" void kernel_launch(void* const* d_in, const int* in_sizes, int n_in,
                              void* d_out, int out_size)
{
    (void)in_sizes; (void)n_in; (void)out_size;
    const float* pred_coords = (const float*)d_in[0];
    const float* pred_logits = (const float*)d_in[1];
    const float* gt_coords   = (const float*)d_in[2];
    const void*  gt_masks    = d_in[4];
    float* out = (float*)d_out;

    prep_kernel   <<<NTOT / 256, 256>>>(pred_coords, pred_logits,
                                        (const unsigned char*)gt_masks);
    setup_kernel  <<<BS, 256>>>();
    scatter_kernel<<<NTOT / 256, 256>>>();
    match_kernel  <<<BS * 32, 256>>>(gt_coords, gt_masks);
    reduce_kernel <<<128, 256>>>(gt_masks, out);
}

// round 13
// speedup vs baseline: 1.3174x; 1.3174x over previous
#include <cuda_runtime.h>
#include <cfloat>
#include <stdint.h>

#define BS    8
#define NQ    16384
#define NG    1024
#define TOPK  4
#define NBIN  1024
#define BINW  0.0009765625f     // 1/1024
#define NQP   (NQ + 64)         // padded candidate row
#define NTOT  (BS * NQ)         // 131072
#define NBG   (BS * NG)         // 8192
#define COST_POINT 0.1f
#define REG_COEF   5.0f

// -------- scratch (static device globals) --------
__device__ float4 g_packed[NTOT];          // {-2x, -2y, |p|^2, prob0}
__device__ float  g_prob[NTOT];
__device__ float2 g_xy[NTOT];              // exact coords for reg loss
__device__ float  g_lp0[NTOT];
__device__ float  g_lp1[NTOT];
__device__ unsigned char g_flag[NTOT];
__device__ int    g_hist[BS][NBIN];        // zero at module load; re-zeroed by scatter
__device__ float4 g_cand4[BS][NQP];        // candidates, descending-prob bucket order
__device__ int    g_candq[BS][NQP];
__device__ int    g_pos[BS][NBIN];         // bucket write cursors (init = bases)
__device__ int    g_tbin[BS];
__device__ int    g_ncand[BS];
__device__ float  g_regp[NBG];
__device__ float  g_part[3 * 128];
__device__ int    g_done;
__device__ int    g_mi32;

__device__ __forceinline__ int mask_at(const void* m, int i, int is_i32) {
    return is_i32 ? (((const int*)m)[i] != 0) : (((const unsigned char*)m)[i] != 0);
}

// -------- prep: per-(b,q) precompute + hist atomics + zeros + mask detect ----
__global__ void __launch_bounds__(256) prep_kernel(
    const float* __restrict__ pc, const float* __restrict__ pl,
    const unsigned char* __restrict__ m)
{
    int t = threadIdx.x;
    if (blockIdx.x == 0) {
        int bad = ((t & 3) != 0) && (m[t] != 0);
        int any = __syncthreads_or(bad);
        if (t == 0) { g_mi32 = !any; g_done = 0; }
    }
    int i = blockIdx.x * blockDim.x + t;
    if (i >= NTOT) return;
    float2 c  = ((const float2*)pc)[i];
    float2 lg = ((const float2*)pl)[i];
    float x = c.x, y = c.y, l0 = lg.x, l1 = lg.y;
    float mm = fmaxf(l0, l1);
    float e0 = expf(l0 - mm);
    float e1 = expf(l1 - mm);
    float s  = __fadd_rn(e0, e1);
    float p0 = __fdiv_rn(e0, s);
    float ls = logf(s);
    float pp = __fadd_rn(__fmul_rn(x, x), __fmul_rn(y, y));
    g_packed[i] = make_float4(__fmul_rn(-2.0f, x), __fmul_rn(-2.0f, y), pp, p0);
    g_prob[i] = p0;
    g_xy[i] = make_float2(x, y);
    g_lp0[i] = __fadd_rn(__fadd_rn(l0, -mm), -ls);
    g_lp1[i] = __fadd_rn(__fadd_rn(l1, -mm), -ls);
    g_flag[i] = 0;
    if (i < NBG) g_regp[i] = 0.0f;
    int bin = min(NBIN - 1, (int)(p0 * 1024.0f));
    atomicAdd(&g_hist[i >> 14][bin], 1);
}

// -------- setup: prefix over per-batch histogram, p4 threshold, bucket bases ----
__global__ void __launch_bounds__(256) setup_kernel() {
    int b = blockIdx.x;
    int t = threadIdx.x;
    __shared__ int ls[256];
    __shared__ int p4bin;
    __shared__ int stbin;
    if (t == 0) p4bin = 0;
    // thread t owns bins [4t..4t+3]; build suffix sums S[i] = sum_{j>=i} hist[j]
    int h0 = g_hist[b][4 * t], h1 = g_hist[b][4 * t + 1];
    int h2 = g_hist[b][4 * t + 2], h3 = g_hist[b][4 * t + 3];
    ls[t] = h0 + h1 + h2 + h3;
    __syncthreads();
    for (int o = 1; o < 256; o <<= 1) {
        int v = (t + o < 256) ? ls[t + o] : 0;
        __syncthreads();
        ls[t] += v;
        __syncthreads();
    }
    int excl = (t + 1 < 256) ? ls[t + 1] : 0;   // sum over threads > t
    int S3 = excl + h3;
    int S2 = S3 + h2;
    int S1 = S2 + h1;
    int S0 = S1 + h0;
    // p4bin = max bin with S[bin] >= 4
    int cand = -1;
    if      (S3 >= 4) cand = 4 * t + 3;
    else if (S2 >= 4) cand = 4 * t + 2;
    else if (S1 >= 4) cand = 4 * t + 1;
    else if (S0 >= 4) cand = 4 * t;
    if (cand >= 0) atomicMax(&p4bin, cand);
    __syncthreads();
    if (t == 0) {
        float lo4 = (float)p4bin * BINW;             // lower bound on p4
        float thresh = lo4 - 0.141422f;              // p4 - 0.1*sqrt(2), conservative
        int tb = (int)floorf(thresh * 1024.0f);
        if (tb < 0) tb = 0;
        stbin = tb;
        g_tbin[b] = tb;
    }
    __syncthreads();
    int tb = stbin;
    // bucket base (descending order): base[bin] = S[bin+1]
    if (4 * t     >= tb) g_pos[b][4 * t]     = S1;
    if (4 * t + 1 >= tb) g_pos[b][4 * t + 1] = S2;
    if (4 * t + 2 >= tb) g_pos[b][4 * t + 2] = S3;
    if (4 * t + 3 >= tb) g_pos[b][4 * t + 3] = excl;
    if (tb >= 4 * t && tb <= 4 * t + 3) {
        int Stb = (tb == 4 * t) ? S0 : (tb == 4 * t + 1) ? S1 : (tb == 4 * t + 2) ? S2 : S3;
        g_ncand[b] = Stb;
    }
}

// -------- scatter: counting-sort into descending buckets + hist re-zero + pads --
__global__ void __launch_bounds__(256) scatter_kernel() {
    int i = blockIdx.x * 256 + threadIdx.x;
    // re-zero histogram for the next launch (deterministic every call)
    if (i < BS * NBIN) ((int*)g_hist)[i] = 0;
    // sentinel padding: w=-1e30 is provably rejected by the filter
    if (blockIdx.x < BS && threadIdx.x < 64) {
        int b = blockIdx.x;
        int idx = g_ncand[b] + threadIdx.x;
        g_cand4[b][idx] = make_float4(0.0f, 0.0f, 0.0f, -1e30f);
        g_candq[b][idx] = 0;
    }
    int b = i >> 14;
    float p = g_prob[i];
    int bin = min(NBIN - 1, (int)(p * 1024.0f));
    if (bin >= g_tbin[b]) {
        int slot = atomicAdd(&g_pos[b][bin], 1);
        g_cand4[b][slot] = g_packed[i];
        g_candq[b][slot] = i & (NQ - 1);
    }
}

// orderable-uint mapping and inverse
__device__ __forceinline__ unsigned int float_key(float f) {
    unsigned int u = __float_as_uint(f);
    return u ^ (((int)u < 0) ? 0xFFFFFFFFu : 0x80000000u);
}
__device__ __forceinline__ float key_to_float(unsigned int k) {
    return __uint_as_float(k ^ ((k & 0x80000000u) ? 0x80000000u : 0xFFFFFFFFu));
}

#define KEY_SENTINEL 0xFF7FFFFFFFFFFFFFull   // (float_key(FLT_MAX)<<32) | 0xFFFFFFFF

// snapshot-exchange merge of two sorted-4 lists across shfl distance d.
// Valid ONLY for disjoint lists (distinct q => distinct keys): stage-d unions
// of disjoint stride-16 subsequences.
#define QUAD_MERGE(d)                                                          \
    {                                                                          \
        unsigned long long s0 = k0, s1 = k1, s2 = k2, s3 = k3;                 \
        unsigned long long p0 = __shfl_xor_sync(0xFFFFFFFFu, s0, d);           \
        unsigned long long p1 = __shfl_xor_sync(0xFFFFFFFFu, s1, d);           \
        unsigned long long p2 = __shfl_xor_sync(0xFFFFFFFFu, s2, d);           \
        unsigned long long p3 = __shfl_xor_sync(0xFFFFFFFFu, s3, d);           \
        unsigned long long ps[4] = {p0, p1, p2, p3};                           \
        _Pragma("unroll")                                                      \
        for (int r = 0; r < 4; r++) {                                          \
            unsigned long long pk = ps[r];                                     \
            if (pk < k3) {                                                     \
                if (pk < k0)      { k3 = k2; k2 = k1; k1 = k0; k0 = pk; }      \
                else if (pk < k1) { k3 = k2; k2 = k1; k1 = pk; }               \
                else if (pk < k2) { k3 = k2; k2 = pk; }                        \
                else              { k3 = pk; }                                 \
            }                                                                  \
        }                                                                      \
    }

// -------- match: batched direct-global ordered scan, 16 threads/g,
// no block syncs; break checked per 4-candidate group AFTER issuing all loads.
__global__ void __launch_bounds__(256) match_kernel(
    const float* __restrict__ gtc, const void* __restrict__ gtm)
{
    int blk = blockIdx.x;                 // 512 blocks: b*64 + sub
    int b   = blk >> 6;
    int sub = blk & 63;
    int t   = threadIdx.x;
    int par = t & 15;
    int g   = sub * 16 + (t >> 4);
    int bg  = b * NG + g;
    int active = mask_at(gtm, bg, g_mi32);
    int n = g_ncand[b];
    const float4* __restrict__ cand  = g_cand4[b];
    const int*    __restrict__ candq = g_candq[b];

    float2 gc = ((const float2*)gtc)[bg];
    float gx = gc.x, gy = gc.y;
    float gg = __fadd_rn(__fmul_rn(gx, gx), __fmul_rn(gy, gy));

    unsigned long long k0 = KEY_SENTINEL, k1 = KEY_SENTINEL,
                       k2 = KEY_SENTINEL, k3 = KEY_SENTINEL;
    float c3  = FLT_MAX;                      // valid upper bound on final c3
    float T   = __fmaf_rn(10.0f, c3, 1e-3f);
    float brk = -FLT_MAX;
    bool done = !active;

    for (int base = 0; base < n; base += 128) {
        if (!done) {
            #pragma unroll
            for (int half = 0; half < 2; half++) {
                int i0 = base + half * 64 + par;
                if (i0 >= n) break;
                // issue ALL 4 independent loads first (MLP), then break-check
                float4 f0 = __ldg(&cand[i0]);
                float4 f1 = __ldg(&cand[i0 + 16]);
                float4 f2 = __ldg(&cand[i0 + 32]);
                float4 f3 = __ldg(&cand[i0 + 48]);
                // descending prob (granularity BINW): if the group's first
                // (max-prob) element is below brk, all later ones are too.
                if (f0.w < brk) { done = true; break; }
                float4 fs[4] = {f0, f1, f2, f3};
                #pragma unroll
                for (int j = 0; j < 4; j++) {
                    float4 f = fs[j];
                    float h = __fmaf_rn(f.x, gx, __fmaf_rn(f.y, gy, f.z));
                    float u = __fmaf_rn(10.0f, f.w, T);
                    float v = __fmaf_rn(u, fabsf(u), -gg);
                    if (h < v) {
                        // exact reference-literal cost
                        float x  = __fmul_rn(-0.5f, f.x), y = __fmul_rn(-0.5f, f.y);
                        float d  = __fmaf_rn(y, gy, __fmul_rn(x, gx));
                        float s1 = __fadd_rn(f.z, gg);
                        float sq = __fmaf_rn(-2.0f, d, s1);
                        float cost = __fadd_rn(__fmul_rn(COST_POINT, __fsqrt_rn(fmaxf(sq, 0.0f))), -f.w);
                        unsigned long long key =
                            ((unsigned long long)float_key(cost) << 32)
                            | (unsigned int)__ldg(&candq[i0 + 16 * j]);
                        if (key < k3) {
                            if (key < k0)      { k3 = k2; k2 = k1; k1 = k0; k0 = key; }
                            else if (key < k1) { k3 = k2; k2 = k1; k1 = key; }
                            else if (key < k2) { k3 = k2; k2 = key; }
                            else               { k3 = key; }
                            // tighten, never loosen, the shared bound
                            c3  = fminf(c3, key_to_float((unsigned int)(k3 >> 32)));
                            T   = __fmaf_rn(10.0f, c3, 1e-3f);
                            brk = __fadd_rn(-c3, -BINW);
                        }
                    }
                }
            }
        }
        // warp-converged: min-share threshold across the 16 lanes of each g
        c3 = fminf(c3, __shfl_xor_sync(0xFFFFFFFFu, c3, 1));
        c3 = fminf(c3, __shfl_xor_sync(0xFFFFFFFFu, c3, 2));
        c3 = fminf(c3, __shfl_xor_sync(0xFFFFFFFFu, c3, 4));
        c3 = fminf(c3, __shfl_xor_sync(0xFFFFFFFFu, c3, 8));
        T   = __fmaf_rn(10.0f, c3, 1e-3f);
        brk = __fadd_rn(-c3, -BINW);
        if (__all_sync(0xFFFFFFFFu, done)) break;
    }

    // final merge of the 16 disjoint per-thread lists (each stage disjoint)
    QUAD_MERGE(1);
    QUAD_MERGE(2);
    QUAD_MERGE(4);
    QUAD_MERGE(8);

    if (active && par == 0) {
        float acc = 0.0f;
        unsigned long long ks[4] = {k0, k1, k2, k3};
        #pragma unroll
        for (int k = 0; k < TOPK; k++) {
            int q = (int)(unsigned int)(ks[k] & 0xFFFFFFFFull);
            g_flag[b * NQ + q] = 1;          // idempotent; races benign
            float2 p = g_xy[b * NQ + q];
            float dx = __fadd_rn(p.x, -gx), dy = __fadd_rn(p.y, -gy);
            acc = __fadd_rn(acc, __fadd_rn(__fmul_rn(dx, dx), __fmul_rn(dy, dy)));
        }
        g_regp[bg] = acc;
    }
}

// -------- reduce: per-block partials + last-block fixed-order finale --------
__global__ void __launch_bounds__(256) reduce_kernel(
    const void* __restrict__ gtm, float* __restrict__ out)
{
    int blk = blockIdx.x;
    int base = blk * 1024;
    int t = threadIdx.x;
    int mi32 = g_mi32;

    float cl = 0.0f, rg = 0.0f; int cn = 0;
    #pragma unroll
    for (int j = 0; j < 4; j++) {
        int i = base + j * 256 + t;
        cl += g_flag[i] ? g_lp0[i] : g_lp1[i];
    }
    if (base < NBG) {
        #pragma unroll
        for (int j = 0; j < 4; j++) {
            int i = base + j * 256 + t;
            rg += g_regp[i];
            cn += mask_at(gtm, i, mi32);
        }
    }
    __shared__ float s1[256], s2[256];
    __shared__ int   s3[256];
    s1[t] = cl; s2[t] = rg; s3[t] = cn;
    __syncthreads();
    for (int s = 128; s > 0; s >>= 1) {
        if (t < s) { s1[t] += s1[t + s]; s2[t] += s2[t + s]; s3[t] += s3[t + s]; }
        __syncthreads();
    }
    __shared__ bool s_last;
    if (t == 0) {
        g_part[blk]       = s1[0];
        g_part[128 + blk] = s2[0];
        g_part[256 + blk] = (float)s3[0];
        __threadfence();
        int old = atomicAdd(&g_done, 1);
        s_last = (old == 127);
    }
    __syncthreads();
    if (s_last) {
        __shared__ float a[128], bb[128], cc[128];
        if (t < 128) {
            a[t]  = g_part[t];
            bb[t] = g_part[128 + t];
            cc[t] = g_part[256 + t];
        }
        __syncthreads();
        for (int s = 64; s > 0; s >>= 1) {
            if (t < s) { a[t] += a[t + s]; bb[t] += bb[t + s]; cc[t] += cc[t + s]; }
            __syncthreads();
        }
        if (t == 0) {
            float n_valid = __fmul_rn(cc[0], (float)TOPK);
            out[0] = __fmul_rn(__fdiv_rn(bb[0], __fmul_rn(n_valid, 2.0f)), REG_COEF);
            out[1] = __fdiv_rn(-a[0], (float)NTOT);
        }
    }
}

extern "C" void kernel_launch(void* const* d_in, const int* in_sizes, int n_in,
                              void* d_out, int out_size)
{
    (void)in_sizes; (void)n_in; (void)out_size;
    const float* pred_coords = (const float*)d_in[0];
    const float* pred_logits = (const float*)d_in[1];
    const float* gt_coords   = (const float*)d_in[2];
    const void*  gt_masks    = d_in[4];
    float* out = (float*)d_out;

    prep_kernel   <<<NTOT / 256, 256>>>(pred_coords, pred_logits,
                                        (const unsigned char*)gt_masks);
    setup_kernel  <<<BS, 256>>>();
    scatter_kernel<<<NTOT / 256, 256>>>();
    match_kernel  <<<BS * 64, 256>>>(gt_coords, gt_masks);
    reduce_kernel <<<128, 256>>>(gt_masks, out);
}